// round 2
// baseline (speedup 1.0000x reference)
#include <cuda_runtime.h>
#include <math.h>

#define BATCH 32
#define CCH   3
#define HH    224
#define NTOK  196
#define PD    768
#define DIM   512
#define NCLS  1000
#define NP    224          // padded token count
#define NPS   (NP*NP)      // 50176
#define SLK_M (64*NP)
#define SLK_QV (64*DIM)
#define ITERS 50
#define LNEPS 1e-5f

typedef unsigned long long u64;

// ---------------- scratch ----------------
__device__ float g_x[BATCH*NTOK*PD];
__device__ float g_Q[BATCH*NP*DIM + SLK_QV];
__device__ float g_V[BATCH*NP*DIM + SLK_QV];
__device__ float g_A[BATCH*NPS + SLK_M];
__device__ float g_Minv[BATCH*NPS + SLK_M];
__device__ float g_P[BATCH*NPS + SLK_M];
__device__ float g_Zbuf[2][BATCH*NPS + SLK_M];
__device__ float g_Ubuf[2][BATCH*NPS + SLK_M];
__device__ float g_pooled[BATCH*DIM];

// ---------------- f32x2 helpers ----------------
__device__ __forceinline__ u64 pack2(float x) {
    u64 r; asm("mov.b64 %0, {%1, %1};" : "=l"(r) : "f"(x)); return r;
}
__device__ __forceinline__ void fma2(u64& d, u64 a, u64 b) {
    asm("fma.rn.f32x2 %0, %1, %2, %0;" : "+l"(d) : "l"(a), "l"(b));
}
__device__ __forceinline__ float2 unpack2(u64 v) {
    float2 f; asm("mov.b64 {%0, %1}, %2;" : "=f"(f.x), "=f"(f.y) : "l"(v)); return f;
}

__device__ __forceinline__ void block_reduce2(float& s, float& s2) {
    __shared__ float sh[2][32];
    int tid = threadIdx.x;
#pragma unroll
    for (int o = 16; o; o >>= 1) {
        s  += __shfl_xor_sync(0xffffffffu, s, o);
        s2 += __shfl_xor_sync(0xffffffffu, s2, o);
    }
    __syncthreads();
    if ((tid & 31) == 0) { sh[0][tid >> 5] = s; sh[1][tid >> 5] = s2; }
    __syncthreads();
    int nw = blockDim.x >> 5;
    float a = 0.f, b = 0.f;
    for (int i = 0; i < nw; i++) { a += sh[0][i]; b += sh[1][i]; }
    s = a; s2 = b;
}

// ---------------- K0: zero ----------------
__global__ void k_zero(float* a, float* b, int n) {
    int i = blockIdx.x * blockDim.x + threadIdx.x;
    if (i < n) { a[i] = 0.f; b[i] = 0.f; }
}

// ---------------- K1: patchify + LN(768) + pos ----------------
__global__ void k_patch_ln(const float* __restrict__ img,
                           const float* __restrict__ lg,
                           const float* __restrict__ lb,
                           const float* __restrict__ pos) {
    int blk = blockIdx.x;
    int b = blk / NTOK, n = blk % NTOK;
    int hh = n / 14, ww = n % 14;
    int tid = threadIdx.x;
    float v[3];
    float s = 0.f, s2 = 0.f;
#pragma unroll
    for (int t = 0; t < 3; t++) {
        int d = tid + t * 256;
        int c = d >> 8, r = d & 255, ph = r >> 4, pw = r & 15;
        float x = img[((b * CCH + c) * HH + hh * 16 + ph) * HH + ww * 16 + pw];
        v[t] = x; s += x; s2 += x * x;
    }
    block_reduce2(s, s2);
    float mu = s * (1.f / 768.f);
    float var = s2 * (1.f / 768.f) - mu * mu;
    float rs = rsqrtf(var + LNEPS);
#pragma unroll
    for (int t = 0; t < 3; t++) {
        int d = tid + t * 256;
        g_x[(b * NTOK + n) * PD + d] = (v[t] - mu) * rs * lg[d] + lb[d] + pos[n * PD + d];
    }
}

// ---------------- K3: LN over 512 ----------------
__global__ void k_ln512(float* __restrict__ buf, const float* __restrict__ lg,
                        const float* __restrict__ lb, float scale) {
    int blk = blockIdx.x;
    int b = blk / NTOK, n = blk % NTOK;
    float* row = buf + (b * NP + n) * DIM;
    int tid = threadIdx.x;   // 128
    float4 v = ((float4*)row)[tid];
    float s = v.x + v.y + v.z + v.w;
    float s2 = v.x * v.x + v.y * v.y + v.z * v.z + v.w * v.w;
    block_reduce2(s, s2);
    float mu = s * (1.f / 512.f);
    float rs = rsqrtf(s2 * (1.f / 512.f) - mu * mu + LNEPS);
    float4 g4 = ((const float4*)lg)[tid], b4 = ((const float4*)lb)[tid];
    v.x = ((v.x - mu) * rs * g4.x + b4.x) * scale;
    v.y = ((v.y - mu) * rs * g4.y + b4.y) * scale;
    v.z = ((v.z - mu) * rs * g4.z + b4.z) * scale;
    v.w = ((v.w - mu) * rs * g4.w + b4.w) * scale;
    ((float4*)row)[tid] = v;
}

// =====================================================================
// Unified packed-f32x2 GEMM. 128x128 tile, BK=8, double-buffered.
// MODE 0: PROJ  C[6272,512] = X[6272,768] @ W[768,512] + bias -> padded QV
// MODE 1: GRAM_A A = 2*V V^T + I           (per batch, 224x224, K=512)
// MODE 2: GRAM_P P = -2*Q V^T + 1/196 (guarded) (per batch)
// MODE 3: ADMM   X=((Z-U)-P)@Minv; Z'=clip(X+U,0,1); U'=U+X-Z'
// =====================================================================
#define SA  130   // u64 stride for A-dup smem
#define SB2 132   // float stride for B smem

template<int MODE>
__global__ __launch_bounds__(256, 1) void k_mm(
    const float* __restrict__ Asrc, const float* __restrict__ A1,
    const float* __restrict__ A2, const float* __restrict__ Bsrc,
    const float* __restrict__ bias,
    float* __restrict__ O0, float* __restrict__ O1)
{
    __shared__ u64   sAd[2][8 * SA];
    __shared__ float sB [2][8 * SB2];

    int tid = threadIdx.x;
    int b = blockIdx.z;
    int m0, n0, K, lda, ldb;
    const float *Ab, *Ub = nullptr, *Pb = nullptr, *Bb;
    if (MODE == 0) {
        m0 = blockIdx.x * 128; n0 = blockIdx.y * 128; K = PD; lda = PD; ldb = DIM;
        Ab = Asrc; Bb = Bsrc;
    } else if (MODE == 3) {
        m0 = blockIdx.x * 96; n0 = blockIdx.y * 96; K = NP; lda = NP; ldb = NP;
        Ab = Asrc + b * NPS; Ub = A1 + b * NPS; Pb = A2 + b * NPS; Bb = Bsrc + b * NPS;
    } else {
        m0 = blockIdx.x * 96; n0 = blockIdx.y * 96; K = DIM; lda = DIM; ldb = DIM;
        Ab = Asrc + b * NP * DIM; Bb = Bsrc + b * NP * DIM;
    }

    int tx = tid & 15, ty = tid >> 4;
    int fm  = tid >> 1, fkq = (tid & 1) * 4;   // A-fill (also GRAM transposed B-fill)
    int fbk = tid >> 5, fbn = (tid & 31) * 4;  // direct B-fill

    u64 acc[8][4];
#pragma unroll
    for (int i = 0; i < 8; i++)
#pragma unroll
        for (int j = 0; j < 4; j++) acc[i][j] = 0ull;

    const int NT = K / 8;

    // ---- fill stage 0 ----
    {
        float4 a4;
        if (MODE == 3) {
            int gi = (m0 + fm) * lda + fkq;
            float4 z4 = *(const float4*)&Ab[gi];
            float4 u4 = *(const float4*)&Ub[gi];
            float4 p4 = *(const float4*)&Pb[gi];
            a4.x = z4.x - u4.x - p4.x; a4.y = z4.y - u4.y - p4.y;
            a4.z = z4.z - u4.z - p4.z; a4.w = z4.w - u4.w - p4.w;
        } else {
            a4 = *(const float4*)&Ab[(m0 + fm) * lda + fkq];
        }
        sAd[0][(fkq + 0) * SA + fm] = pack2(a4.x);
        sAd[0][(fkq + 1) * SA + fm] = pack2(a4.y);
        sAd[0][(fkq + 2) * SA + fm] = pack2(a4.z);
        sAd[0][(fkq + 3) * SA + fm] = pack2(a4.w);
        if (MODE == 1 || MODE == 2) {
            float4 v4 = *(const float4*)&Bb[(n0 + fm) * ldb + fkq];
            sB[0][(fkq + 0) * SB2 + fm] = v4.x; sB[0][(fkq + 1) * SB2 + fm] = v4.y;
            sB[0][(fkq + 2) * SB2 + fm] = v4.z; sB[0][(fkq + 3) * SB2 + fm] = v4.w;
        } else {
            *(float4*)&sB[0][fbk * SB2 + fbn] = *(const float4*)&Bb[fbk * ldb + n0 + fbn];
        }
    }
    __syncthreads();

    int st = 0;
    for (int t = 0; t < NT; t++) {
        int k0n = (t + 1) * 8;
        bool more = (t + 1 < NT);
        float4 pa, pz, pu, pp, pb;
        if (more) {
            if (MODE == 3) {
                int gi = (m0 + fm) * lda + k0n + fkq;
                pz = *(const float4*)&Ab[gi];
                pu = *(const float4*)&Ub[gi];
                pp = *(const float4*)&Pb[gi];
                pb = *(const float4*)&Bb[(k0n + fbk) * ldb + n0 + fbn];
            } else if (MODE == 0) {
                pa = *(const float4*)&Ab[(m0 + fm) * lda + k0n + fkq];
                pb = *(const float4*)&Bb[(k0n + fbk) * ldb + n0 + fbn];
            } else {
                pa = *(const float4*)&Ab[(m0 + fm) * lda + k0n + fkq];
                pb = *(const float4*)&Bb[(n0 + fm) * ldb + k0n + fkq];
            }
        }
#pragma unroll
        for (int kk = 0; kk < 8; kk++) {
            const ulonglong2* pA = (const ulonglong2*)&sAd[st][kk * SA + ty * 8];
            ulonglong2 a01 = pA[0], a23 = pA[1], a45 = pA[2], a67 = pA[3];
            const ulonglong2* pB = (const ulonglong2*)&sB[st][kk * SB2 + tx * 8];
            ulonglong2 b01 = pB[0], b23 = pB[1];
            u64 av[8] = {a01.x, a01.y, a23.x, a23.y, a45.x, a45.y, a67.x, a67.y};
            u64 bv[4] = {b01.x, b01.y, b23.x, b23.y};
#pragma unroll
            for (int i = 0; i < 8; i++) {
                fma2(acc[i][0], av[i], bv[0]);
                fma2(acc[i][1], av[i], bv[1]);
                fma2(acc[i][2], av[i], bv[2]);
                fma2(acc[i][3], av[i], bv[3]);
            }
        }
        if (more) {
            int ns = st ^ 1;
            float4 a4;
            if (MODE == 3) {
                a4.x = pz.x - pu.x - pp.x; a4.y = pz.y - pu.y - pp.y;
                a4.z = pz.z - pu.z - pp.z; a4.w = pz.w - pu.w - pp.w;
            } else a4 = pa;
            sAd[ns][(fkq + 0) * SA + fm] = pack2(a4.x);
            sAd[ns][(fkq + 1) * SA + fm] = pack2(a4.y);
            sAd[ns][(fkq + 2) * SA + fm] = pack2(a4.z);
            sAd[ns][(fkq + 3) * SA + fm] = pack2(a4.w);
            if (MODE == 1 || MODE == 2) {
                sB[ns][(fkq + 0) * SB2 + fm] = pb.x; sB[ns][(fkq + 1) * SB2 + fm] = pb.y;
                sB[ns][(fkq + 2) * SB2 + fm] = pb.z; sB[ns][(fkq + 3) * SB2 + fm] = pb.w;
            } else {
                *(float4*)&sB[ns][fbk * SB2 + fbn] = pb;
            }
        }
        __syncthreads();
        st ^= 1;
    }

    // ---- epilogue ----
    float bsv[8];
    if (MODE == 0) {
#pragma unroll
        for (int j = 0; j < 8; j++) bsv[j] = bias[n0 + tx * 8 + j];
    }
#pragma unroll
    for (int i = 0; i < 8; i++) {
        float c[8];
#pragma unroll
        for (int jp = 0; jp < 4; jp++) {
            float2 f = unpack2(acc[i][jp]);
            c[2 * jp] = f.x; c[2 * jp + 1] = f.y;
        }
        if (MODE == 0) {
            int gm = m0 + ty * 8 + i;
            int bb = gm / NTOK, nn = gm % NTOK;
            float* orow = O0 + (bb * NP + nn) * DIM + n0 + tx * 8;
            float4 o0 = {c[0] + bsv[0], c[1] + bsv[1], c[2] + bsv[2], c[3] + bsv[3]};
            float4 o1 = {c[4] + bsv[4], c[5] + bsv[5], c[6] + bsv[6], c[7] + bsv[7]};
            *(float4*)&orow[0] = o0;
            *(float4*)&orow[4] = o1;
        } else if (MODE == 1) {
            int gm = m0 + ty * 8 + i;
            int gc = n0 + tx * 8;
            float o[8];
#pragma unroll
            for (int j = 0; j < 8; j++)
                o[j] = 2.f * c[j] + ((gm == gc + j) ? 1.f : 0.f);
            float* orow = O0 + b * NPS + gm * NP + gc;
            *(float4*)&orow[0] = make_float4(o[0], o[1], o[2], o[3]);
            *(float4*)&orow[4] = make_float4(o[4], o[5], o[6], o[7]);
        } else if (MODE == 2) {
            int gm = m0 + ty * 8 + i;
            int gc = n0 + tx * 8;
            float o[8];
#pragma unroll
            for (int j = 0; j < 8; j++)
                o[j] = (gm < NTOK && (gc + j) < NTOK) ? (-2.f * c[j] + (1.f / 196.f)) : 0.f;
            float* orow = O0 + b * NPS + gm * NP + gc;
            *(float4*)&orow[0] = make_float4(o[0], o[1], o[2], o[3]);
            *(float4*)&orow[4] = make_float4(o[4], o[5], o[6], o[7]);
        } else {
            int gm = m0 + ty * 8 + i;
            int o = gm * NP + n0 + tx * 8;
            float4 u0 = *(const float4*)&Ub[o];
            float4 u1 = *(const float4*)&Ub[o + 4];
            float uu[8] = {u0.x, u0.y, u0.z, u0.w, u1.x, u1.y, u1.z, u1.w};
            float zo[8], un[8];
#pragma unroll
            for (int j = 0; j < 8; j++) {
                float zz = c[j] + uu[j];
                zz = fminf(fmaxf(zz, 0.f), 1.f);
                zo[j] = zz;
                un[j] = uu[j] + c[j] - zz;
            }
            float* zrow = O0 + b * NPS + o;
            float* urow = O1 + b * NPS + o;
            *(float4*)&zrow[0] = make_float4(zo[0], zo[1], zo[2], zo[3]);
            *(float4*)&zrow[4] = make_float4(zo[4], zo[5], zo[6], zo[7]);
            *(float4*)&urow[0] = make_float4(un[0], un[1], un[2], un[3]);
            *(float4*)&urow[4] = make_float4(un[4], un[5], un[6], un[7]);
        }
    }
}

// ---------------- K6: Gauss-Jordan inverse ----------------
extern __shared__ float sA[];   // 196*197 floats
__global__ void k_inv(const float* __restrict__ Ain, float* __restrict__ Mout) {
    int b = blockIdx.x;
    int tid = threadIdx.x;      // 512
    const float* A = Ain + b * NPS;
    float* Mi = Mout + b * NPS;
    for (int i = tid; i < 196 * 196; i += 512) {
        int r = i / 196, c = i % 196;
        sA[r * 197 + c] = A[r * NP + c];
    }
    __shared__ float s_pivinv;
    int wid = tid >> 5, lane = tid & 31;
    for (int k = 0; k < 196; k++) {
        __syncthreads();
        if (tid == 0) s_pivinv = 1.0f / sA[k * 197 + k];
        __syncthreads();
        float pv = s_pivinv;
        if (tid < 196)
            sA[k * 197 + tid] = ((tid == k) ? 1.0f : sA[k * 197 + tid]) * pv;
        __syncthreads();
        float rk[7];
#pragma unroll
        for (int t = 0; t < 7; t++) {
            int j = lane + 32 * t;
            rk[t] = (j < 196) ? sA[k * 197 + j] : 0.f;
        }
        for (int i = wid; i < 196; i += 16) {
            if (i == k) continue;
            float f = sA[i * 197 + k];
#pragma unroll
            for (int t = 0; t < 7; t++) {
                int j = lane + 32 * t;
                if (j < 196) {
                    float val = ((j == k) ? 0.f : sA[i * 197 + j]) - f * rk[t];
                    sA[i * 197 + j] = val;
                }
            }
        }
    }
    __syncthreads();
    for (int i = tid; i < NPS; i += 512) {
        int r = i / NP, c = i % NP;
        Mi[i] = (r < 196 && c < 196) ? sA[r * 197 + c] : 0.f;
    }
}

// ---------------- K8: pooled ----------------
__global__ void k_pool(const float* __restrict__ Zfin) {
    int b = blockIdx.x;
    int tid = threadIdx.x;   // 256
    __shared__ float sS[196], sW[196];
    const float* Zb = Zfin + b * NPS;
    if (tid < 196) {
        float s = 0.f;
        const float* row = Zb + tid * NP;
        for (int m = 0; m < 196; m++) s += fabsf(row[m]);
        sS[tid] = s + 1e-10f;
    }
    __syncthreads();
    if (tid < 196) {
        float w = 0.f;
        for (int n = 0; n < 196; n++) w += Zb[n * NP + tid] / sS[n];
        sW[tid] = w * (1.f / 196.f);
    }
    __syncthreads();
    const float* Vb = g_V + b * NP * DIM;
    for (int d = tid; d < DIM; d += 256) {
        float acc = 0.f;
        for (int m = 0; m < 196; m++) acc += sW[m] * Vb[m * DIM + d];
        g_pooled[b * DIM + d] = acc;
    }
}

// ---------------- K9: head ----------------
__global__ void k_head(const float* __restrict__ lg, const float* __restrict__ lb,
                       const float* __restrict__ W, const float* __restrict__ bias,
                       float* __restrict__ out) {
    int b = blockIdx.x;
    int tid = threadIdx.x;   // 256
    __shared__ float sx[DIM];
    float s = 0.f, s2 = 0.f;
    for (int d = tid; d < DIM; d += 256) {
        float v = g_pooled[b * DIM + d];
        sx[d] = v; s += v; s2 += v * v;
    }
    block_reduce2(s, s2);
    float mu = s * (1.f / 512.f);
    float rs = rsqrtf(s2 * (1.f / 512.f) - mu * mu + LNEPS);
    __syncthreads();
    for (int d = tid; d < DIM; d += 256) sx[d] = (sx[d] - mu) * rs * lg[d] + lb[d];
    __syncthreads();
    float lgts[4];
    float mx = -1e30f;
#pragma unroll
    for (int t = 0; t < 4; t++) {
        int c = tid + t * 256;
        if (c < NCLS) {
            float acc = bias[c];
            for (int d = 0; d < DIM; d++) acc += sx[d] * W[d * NCLS + c];
            lgts[t] = acc;
            mx = fmaxf(mx, acc);
        } else lgts[t] = -1e30f;
    }
    __shared__ float red[32];
    for (int o = 16; o; o >>= 1) mx = fmaxf(mx, __shfl_xor_sync(0xffffffffu, mx, o));
    if ((tid & 31) == 0) red[tid >> 5] = mx;
    __syncthreads();
    float bm = red[0];
    for (int i = 1; i < 8; i++) bm = fmaxf(bm, red[i]);
    float es = 0.f;
#pragma unroll
    for (int t = 0; t < 4; t++) {
        int c = tid + t * 256;
        if (c < NCLS) { lgts[t] = expf(lgts[t] - bm); es += lgts[t]; }
    }
    float dummy = 0.f;
    block_reduce2(es, dummy);
#pragma unroll
    for (int t = 0; t < 4; t++) {
        int c = tid + t * 256;
        if (c < NCLS) out[b * NCLS + c] = lgts[t] / es;
    }
}

// ---------------- host ----------------
extern "C" void kernel_launch(void* const* d_in, const int* in_sizes, int n_in,
                              void* d_out, int out_size) {
    const float* img    = (const float*)d_in[0];
    const float* ln_pg  = (const float*)d_in[1];
    const float* ln_pb  = (const float*)d_in[2];
    const float* wq_w   = (const float*)d_in[3];
    const float* wq_b   = (const float*)d_in[4];
    const float* lnq_g  = (const float*)d_in[5];
    const float* lnq_b  = (const float*)d_in[6];
    const float* wv_w   = (const float*)d_in[7];
    const float* wv_b   = (const float*)d_in[8];
    const float* lnv_g  = (const float*)d_in[9];
    const float* lnv_b  = (const float*)d_in[10];
    const float* pos    = (const float*)d_in[11];
    const float* mlp_g  = (const float*)d_in[12];
    const float* mlp_b  = (const float*)d_in[13];
    const float* mlp_w  = (const float*)d_in[14];
    const float* mlp_bs = (const float*)d_in[15];
    float* out = (float*)d_out;

    float *px, *pq, *pv, *pa, *pm, *pp, *pz, *pu;
    cudaGetSymbolAddress((void**)&px, g_x);
    cudaGetSymbolAddress((void**)&pq, g_Q);
    cudaGetSymbolAddress((void**)&pv, g_V);
    cudaGetSymbolAddress((void**)&pa, g_A);
    cudaGetSymbolAddress((void**)&pm, g_Minv);
    cudaGetSymbolAddress((void**)&pp, g_P);
    cudaGetSymbolAddress((void**)&pz, g_Zbuf);
    cudaGetSymbolAddress((void**)&pu, g_Ubuf);
    const int ZSTR = BATCH * NPS + SLK_M;
    float* pz0 = pz;        float* pz1 = pz + ZSTR;
    float* pu0 = pu;        float* pu1 = pu + ZSTR;

    cudaFuncSetAttribute(k_inv, cudaFuncAttributeMaxDynamicSharedMemorySize, 196 * 197 * 4);

    // zero ADMM state
    k_zero<<<(ZSTR + 255) / 256, 256>>>(pz0, pu0, ZSTR);
    // 1) patchify + LN + pos
    k_patch_ln<<<BATCH * NTOK, 256>>>(img, ln_pg, ln_pb, pos);
    // 2) projections (packed f32x2 GEMM)
    k_mm<0><<<dim3(49, 4, 1), 256>>>(px, nullptr, nullptr, wq_w, wq_b, pq, nullptr);
    k_mm<0><<<dim3(49, 4, 1), 256>>>(px, nullptr, nullptr, wv_w, wv_b, pv, nullptr);
    // 3) LayerNorms (V also scaled by 1/196)
    k_ln512<<<BATCH * NTOK, 128>>>(pq, lnq_g, lnq_b, 1.0f);
    k_ln512<<<BATCH * NTOK, 128>>>(pv, lnv_g, lnv_b, 1.0f / 196.0f);
    // 4) Gram matrices
    k_mm<1><<<dim3(2, 2, BATCH), 256>>>(pv, nullptr, nullptr, pv, nullptr, pa, nullptr);
    k_mm<2><<<dim3(2, 2, BATCH), 256>>>(pq, nullptr, nullptr, pv, nullptr, pp, nullptr);
    // 5) inverse
    k_inv<<<BATCH, 512, 196 * 197 * 4>>>(pa, pm);
    // 6) ADMM iterations (double-buffered)
    for (int t = 0; t < ITERS; t++) {
        const float* zi = (t & 1) ? pz1 : pz0;
        const float* ui = (t & 1) ? pu1 : pu0;
        float* zo = (t & 1) ? pz0 : pz1;
        float* uo = (t & 1) ? pu0 : pu1;
        k_mm<3><<<dim3(2, 2, BATCH), 256>>>(zi, ui, pp, pm, nullptr, zo, uo);
    }
    // 7) pooled (final Z in buffer 0)
    k_pool<<<BATCH, 256>>>(pz0);
    // 8) head
    k_head<<<BATCH, 256>>>(mlp_g, mlp_b, mlp_w, mlp_bs, out);
}

// round 4
// speedup vs baseline: 1.3039x; 1.3039x over previous
#include <cuda_runtime.h>
#include <cuda_bf16.h>
#include <math.h>
#include <cstdint>

#define BATCH 32
#define CCH   3
#define HH    224
#define NTOK  196
#define PD    768
#define DIM   512
#define NCLS  1000
#define NP    224
#define NPS   (NP*NP)
#define KP    256
#define SLK_M (64*NP)
#define SLK_QV (64*DIM)
#define ITERS 50
#define LNEPS 1e-5f

typedef unsigned long long u64;
typedef unsigned int u32;

// ---------------- scratch ----------------
__device__ float g_x[BATCH*NTOK*PD];
__device__ float g_Q[BATCH*NP*DIM + SLK_QV];
__device__ float g_V[BATCH*NP*DIM + SLK_QV];
__device__ float g_A[BATCH*NPS + SLK_M];
__device__ float g_Minv[BATCH*NPS + SLK_M];
__device__ float g_P[BATCH*NPS + SLK_M];
__device__ float g_Zbuf[2][BATCH*NPS + SLK_M];
__device__ float g_Ubuf[2][BATCH*NPS + SLK_M];
__device__ __align__(16) __nv_bfloat16 g_MH[BATCH*NP*KP];
__device__ __align__(16) __nv_bfloat16 g_ML[BATCH*NP*KP];
__device__ float g_pooled[BATCH*DIM];

// ---------------- helpers ----------------
__device__ __forceinline__ void block_reduce2(float& s, float& s2) {
    __shared__ float sh[2][32];
    int tid = threadIdx.x;
#pragma unroll
    for (int o = 16; o; o >>= 1) {
        s  += __shfl_xor_sync(0xffffffffu, s, o);
        s2 += __shfl_xor_sync(0xffffffffu, s2, o);
    }
    __syncthreads();
    if ((tid & 31) == 0) { sh[0][tid >> 5] = s; sh[1][tid >> 5] = s2; }
    __syncthreads();
    int nw = blockDim.x >> 5;
    float a = 0.f, b = 0.f;
    for (int i = 0; i < nw; i++) { a += sh[0][i]; b += sh[1][i]; }
    s = a; s2 = b;
}

__global__ void k_zero(float* a, float* b, int n) {
    int i = blockIdx.x * blockDim.x + threadIdx.x;
    if (i < n) { a[i] = 0.f; b[i] = 0.f; }
}

// ---------------- patchify + LN(768) + pos ----------------
__global__ void k_patch_ln(const float* __restrict__ img,
                           const float* __restrict__ lg,
                           const float* __restrict__ lb,
                           const float* __restrict__ pos) {
    int blk = blockIdx.x;
    int b = blk / NTOK, n = blk % NTOK;
    int hh = n / 14, ww = n % 14;
    int tid = threadIdx.x;
    float v[3];
    float s = 0.f, s2 = 0.f;
#pragma unroll
    for (int t = 0; t < 3; t++) {
        int d = tid + t * 256;
        int c = d >> 8, r = d & 255, ph = r >> 4, pw = r & 15;
        float x = img[((b * CCH + c) * HH + hh * 16 + ph) * HH + ww * 16 + pw];
        v[t] = x; s += x; s2 += x * x;
    }
    block_reduce2(s, s2);
    float mu = s * (1.f / 768.f);
    float var = s2 * (1.f / 768.f) - mu * mu;
    float rs = rsqrtf(var + LNEPS);
#pragma unroll
    for (int t = 0; t < 3; t++) {
        int d = tid + t * 256;
        g_x[(b * NTOK + n) * PD + d] = (v[t] - mu) * rs * lg[d] + lb[d] + pos[n * PD + d];
    }
}

// ---------------- projection GEMM ----------------
__global__ void k_proj(const float* __restrict__ X, const float* __restrict__ W,
                       const float* __restrict__ bias, float* __restrict__ out) {
    __shared__ float As[16][68], Bs[16][68];
    int m0 = blockIdx.x * 64, n0 = blockIdx.y * 64;
    int tid = threadIdx.x;
    int tx = tid & 15, ty = tid >> 4;
    int arow = tid >> 2, acg = (tid & 3) * 4;
    int brow = tid >> 4, bcol = (tid & 15) * 4;
    float acc[4][4] = {};
    for (int k0 = 0; k0 < PD; k0 += 16) {
        float4 a = *(const float4*)&X[(m0 + arow) * PD + k0 + acg];
        As[acg + 0][arow] = a.x; As[acg + 1][arow] = a.y;
        As[acg + 2][arow] = a.z; As[acg + 3][arow] = a.w;
        *(float4*)&Bs[brow][bcol] = *(const float4*)&W[(k0 + brow) * DIM + n0 + bcol];
        __syncthreads();
#pragma unroll
        for (int kk = 0; kk < 16; kk++) {
            float4 a4 = *(float4*)&As[kk][ty * 4];
            float4 b4 = *(float4*)&Bs[kk][tx * 4];
            acc[0][0] += a4.x * b4.x; acc[0][1] += a4.x * b4.y; acc[0][2] += a4.x * b4.z; acc[0][3] += a4.x * b4.w;
            acc[1][0] += a4.y * b4.x; acc[1][1] += a4.y * b4.y; acc[1][2] += a4.y * b4.z; acc[1][3] += a4.y * b4.w;
            acc[2][0] += a4.z * b4.x; acc[2][1] += a4.z * b4.y; acc[2][2] += a4.z * b4.z; acc[2][3] += a4.z * b4.w;
            acc[3][0] += a4.w * b4.x; acc[3][1] += a4.w * b4.y; acc[3][2] += a4.w * b4.z; acc[3][3] += a4.w * b4.w;
        }
        __syncthreads();
    }
#pragma unroll
    for (int i = 0; i < 4; i++) {
        int gm = m0 + ty * 4 + i;
        int b = gm / NTOK, nn = gm % NTOK;
#pragma unroll
        for (int j = 0; j < 4; j++) {
            int gc = n0 + tx * 4 + j;
            out[(b * NP + nn) * DIM + gc] = acc[i][j] + bias[gc];
        }
    }
}

// ---------------- LN over 512 ----------------
__global__ void k_ln512(float* __restrict__ buf, const float* __restrict__ lg,
                        const float* __restrict__ lb, float scale) {
    int blk = blockIdx.x;
    int b = blk / NTOK, n = blk % NTOK;
    float* row = buf + (b * NP + n) * DIM;
    int tid = threadIdx.x;
    float4 v = ((float4*)row)[tid];
    float s = v.x + v.y + v.z + v.w;
    float s2 = v.x * v.x + v.y * v.y + v.z * v.z + v.w * v.w;
    block_reduce2(s, s2);
    float mu = s * (1.f / 512.f);
    float rs = rsqrtf(s2 * (1.f / 512.f) - mu * mu + LNEPS);
    float4 g4 = ((const float4*)lg)[tid], b4 = ((const float4*)lb)[tid];
    v.x = ((v.x - mu) * rs * g4.x + b4.x) * scale;
    v.y = ((v.y - mu) * rs * g4.y + b4.y) * scale;
    v.z = ((v.z - mu) * rs * g4.z + b4.z) * scale;
    v.w = ((v.w - mu) * rs * g4.w + b4.w) * scale;
    ((float4*)row)[tid] = v;
}

// ---------------- Gram GEMMs ----------------
__global__ void k_gram(const float* __restrict__ Abase, const float* __restrict__ Bbase,
                       float* __restrict__ out, int mode) {
    int b = blockIdx.z;
    const float* Ab = Abase + b * NP * DIM;
    const float* Bb = Bbase + b * NP * DIM;
    __shared__ float As[16][68], Bs[16][68];
    int m0 = blockIdx.x * 64, n0 = blockIdx.y * 64;
    int tid = threadIdx.x;
    int tx = tid & 15, ty = tid >> 4;
    int arow = tid >> 2, acg = (tid & 3) * 4;
    float acc[4][4] = {};
    for (int k0 = 0; k0 < DIM; k0 += 16) {
        float4 a = *(const float4*)&Ab[(m0 + arow) * DIM + k0 + acg];
        As[acg + 0][arow] = a.x; As[acg + 1][arow] = a.y;
        As[acg + 2][arow] = a.z; As[acg + 3][arow] = a.w;
        float4 bb = *(const float4*)&Bb[(n0 + arow) * DIM + k0 + acg];
        Bs[acg + 0][arow] = bb.x; Bs[acg + 1][arow] = bb.y;
        Bs[acg + 2][arow] = bb.z; Bs[acg + 3][arow] = bb.w;
        __syncthreads();
#pragma unroll
        for (int kk = 0; kk < 16; kk++) {
            float4 a4 = *(float4*)&As[kk][ty * 4];
            float4 b4 = *(float4*)&Bs[kk][tx * 4];
            acc[0][0] += a4.x * b4.x; acc[0][1] += a4.x * b4.y; acc[0][2] += a4.x * b4.z; acc[0][3] += a4.x * b4.w;
            acc[1][0] += a4.y * b4.x; acc[1][1] += a4.y * b4.y; acc[1][2] += a4.y * b4.z; acc[1][3] += a4.y * b4.w;
            acc[2][0] += a4.z * b4.x; acc[2][1] += a4.z * b4.y; acc[2][2] += a4.z * b4.z; acc[2][3] += a4.z * b4.w;
            acc[3][0] += a4.w * b4.x; acc[3][1] += a4.w * b4.y; acc[3][2] += a4.w * b4.z; acc[3][3] += a4.w * b4.w;
        }
        __syncthreads();
    }
#pragma unroll
    for (int i = 0; i < 4; i++) {
        int gm = m0 + ty * 4 + i;
        if (gm >= NP) continue;
#pragma unroll
        for (int j = 0; j < 4; j++) {
            int gn = n0 + tx * 4 + j;
            if (gn >= NP) continue;
            float val;
            if (mode == 0) {
                val = 2.f * acc[i][j] + ((gm == gn) ? 1.f : 0.f);
            } else {
                val = (gm < NTOK && gn < NTOK) ? (-2.f * acc[i][j] + (1.f / 196.f)) : 0.f;
            }
            out[b * NPS + gm * NP + gn] = val;
        }
    }
}

// ---------------- Gauss-Jordan inverse ----------------
extern __shared__ float sA[];
__global__ void k_inv(const float* __restrict__ Ain, float* __restrict__ Mout) {
    int b = blockIdx.x;
    int tid = threadIdx.x;
    const float* A = Ain + b * NPS;
    float* Mi = Mout + b * NPS;
    for (int i = tid; i < 196 * 196; i += 512) {
        int r = i / 196, c = i % 196;
        sA[r * 197 + c] = A[r * NP + c];
    }
    __shared__ float s_pivinv;
    int wid = tid >> 5, lane = tid & 31;
    for (int k = 0; k < 196; k++) {
        __syncthreads();
        if (tid == 0) s_pivinv = 1.0f / sA[k * 197 + k];
        __syncthreads();
        float pv = s_pivinv;
        if (tid < 196)
            sA[k * 197 + tid] = ((tid == k) ? 1.0f : sA[k * 197 + tid]) * pv;
        __syncthreads();
        float rk[7];
#pragma unroll
        for (int t = 0; t < 7; t++) {
            int j = lane + 32 * t;
            rk[t] = (j < 196) ? sA[k * 197 + j] : 0.f;
        }
        for (int i = wid; i < 196; i += 16) {
            if (i == k) continue;
            float f = sA[i * 197 + k];
#pragma unroll
            for (int t = 0; t < 7; t++) {
                int j = lane + 32 * t;
                if (j < 196) {
                    float val = ((j == k) ? 0.f : sA[i * 197 + j]) - f * rk[t];
                    sA[i * 197 + j] = val;
                }
            }
        }
    }
    __syncthreads();
    for (int i = tid; i < NPS; i += 512) {
        int r = i / NP, c = i % NP;
        Mi[i] = (r < 196 && c < 196) ? sA[r * 197 + c] : 0.f;
    }
}

// ---------------- split Minv -> bf16 hi/lo, padded [B][224][256] ----------------
__global__ void k_minv_split(const float* __restrict__ Minv) {
    int idx = blockIdx.x * 256 + threadIdx.x;
    if (idx >= BATCH * NP * KP) return;
    int k = idx & (KP - 1);
    int r = (idx >> 8) % NP;
    int b = idx / (NP * KP);
    float v = (k < NP) ? Minv[b * NPS + r * NP + k] : 0.f;
    __nv_bfloat16 h = __float2bfloat16(v);
    g_MH[idx] = h;
    g_ML[idx] = __float2bfloat16(v - __bfloat162float(h));
}

// =====================================================================
// warp-mma bf16 hi/lo ADMM iteration.
// Grid (ns=2, mt=2, b=32), block 256 (8 warps: 4 m-warps x 2 n-warps).
// CTA computes X[128,112] = RHS[128,256] @ MinvT[112,256], then Z/U update.
// =====================================================================
#define SAS   72                      // bf16 smem row stride
#define AH_OFF 0
#define AL_OFF (128*SAS)
#define BH_OFF (2*128*SAS)
#define BL_OFF (2*128*SAS + 112*SAS)
#define STG_ELEMS (2*128*SAS + 2*112*SAS)      // 34560 bf16
#define ADMM_SMEM (2*STG_ELEMS*2)              // 138240 bytes

__device__ __forceinline__ void split4(float x0, float x1, float x2, float x3,
                                       u64& h, u64& l) {
    __nv_bfloat162 h01 = __floats2bfloat162_rn(x0, x1);
    __nv_bfloat162 h23 = __floats2bfloat162_rn(x2, x3);
    float r0 = x0 - __bfloat162float(h01.x);
    float r1 = x1 - __bfloat162float(h01.y);
    float r2 = x2 - __bfloat162float(h23.x);
    float r3 = x3 - __bfloat162float(h23.y);
    __nv_bfloat162 l01 = __floats2bfloat162_rn(r0, r1);
    __nv_bfloat162 l23 = __floats2bfloat162_rn(r2, r3);
    h = ((u64)*reinterpret_cast<u32*>(&h23) << 32) | *reinterpret_cast<u32*>(&h01);
    l = ((u64)*reinterpret_cast<u32*>(&l23) << 32) | *reinterpret_cast<u32*>(&l01);
}

__device__ __forceinline__ void mma16816(float* d, const u32* a, const u32* b) {
    asm volatile("mma.sync.aligned.m16n8k16.row.col.f32.bf16.bf16.f32 "
        "{%0,%1,%2,%3}, {%4,%5,%6,%7}, {%8,%9}, {%0,%1,%2,%3};"
        : "+f"(d[0]), "+f"(d[1]), "+f"(d[2]), "+f"(d[3])
        : "r"(a[0]), "r"(a[1]), "r"(a[2]), "r"(a[3]), "r"(b[0]), "r"(b[1]));
}

__global__ __launch_bounds__(256) void k_admm_mma(
    const float* __restrict__ Zin, const float* __restrict__ Uin,
    const float* __restrict__ Pg,
    const __nv_bfloat16* __restrict__ MH, const __nv_bfloat16* __restrict__ ML,
    float* __restrict__ Zout, float* __restrict__ Uout)
{
    extern __shared__ __nv_bfloat16 sm[];
    int tid = threadIdx.x;
    int lane = tid & 31, wid = tid >> 5;
    int wm = wid & 3, wn = wid >> 2;
    int grp = lane >> 2, qid = lane & 3;
    int ns = blockIdx.x, mtb = blockIdx.y, b = blockIdx.z;

    // A-fill indices: this thread covers row ar, k-half ah (32 k)
    const int ar = tid >> 1;
    const int ah = (tid & 1) * 32;
    const float* zr = Zin + (size_t)b * NPS + (mtb * 128 + ar) * NP;
    const float* ur = Uin + (size_t)b * NPS + (mtb * 128 + ar) * NP;
    const float* pr = Pg  + (size_t)b * NPS + (mtb * 128 + ar) * NP;
    const __nv_bfloat16* MHrow = MH + ((size_t)b * NP + ns * 112) * KP;
    const __nv_bfloat16* MLrow = ML + ((size_t)b * NP + ns * 112) * KP;

    float acc[2][7][4];
#pragma unroll
    for (int i = 0; i < 2; i++)
#pragma unroll
        for (int j = 0; j < 7; j++)
#pragma unroll
            for (int q = 0; q < 4; q++) acc[i][j][q] = 0.f;

    // ---------------- fill lambda ----------------
    auto fill = [&](int s, int kb) {
        __nv_bfloat16* base = sm + s * STG_ELEMS;
        __nv_bfloat16* AH = base + AH_OFF;
        __nv_bfloat16* AL = base + AL_OFF;
        __nv_bfloat16* BH = base + BH_OFF;
        __nv_bfloat16* BL = base + BL_OFF;
#pragma unroll
        for (int p = 0; p < 8; p++) {
            int gk = kb + ah + p * 4;
            float4 z4 = *(const float4*)(zr + gk);
            float4 u4 = *(const float4*)(ur + gk);
            float4 p4 = *(const float4*)(pr + gk);
            u64 hv, lv;
            split4(z4.x - u4.x - p4.x, z4.y - u4.y - p4.y,
                   z4.z - u4.z - p4.z, z4.w - u4.w - p4.w, hv, lv);
            *(u64*)&AH[ar * SAS + ah + p * 4] = hv;
            *(u64*)&AL[ar * SAS + ah + p * 4] = lv;
        }
#pragma unroll
        for (int it = 0; it < 7; it++) {
            int idx = tid + it * 256;              // < 112*16 = 1792
            int rr = idx >> 4, p = idx & 15;
            *(u64*)&BH[rr * SAS + p * 4] = *(const u64*)&MHrow[rr * KP + kb + p * 4];
            *(u64*)&BL[rr * SAS + p * 4] = *(const u64*)&MLrow[rr * KP + kb + p * 4];
        }
    };

    fill(0, 0);
    __syncthreads();

    for (int c = 0; c < 4; c++) {
        if (c < 3) fill((c + 1) & 1, (c + 1) * 64);
        const __nv_bfloat16* base = sm + (c & 1) * STG_ELEMS;
        const __nv_bfloat16* AH = base + AH_OFF;
        const __nv_bfloat16* AL = base + AL_OFF;
        const __nv_bfloat16* BH = base + BH_OFF;
        const __nv_bfloat16* BL = base + BL_OFF;
#pragma unroll
        for (int ks = 0; ks < 4; ks++) {
            int kofs = ks * 16 + qid * 2;
            u32 ahf[2][4], alf[2][4], bhf[7][2], blf[7][2];
#pragma unroll
            for (int mt = 0; mt < 2; mt++) {
                int r0 = (wm * 32 + mt * 16 + grp) * SAS + kofs;
                ahf[mt][0] = *(const u32*)&AH[r0];
                ahf[mt][1] = *(const u32*)&AH[r0 + 8 * SAS];
                ahf[mt][2] = *(const u32*)&AH[r0 + 8];
                ahf[mt][3] = *(const u32*)&AH[r0 + 8 * SAS + 8];
                alf[mt][0] = *(const u32*)&AL[r0];
                alf[mt][1] = *(const u32*)&AL[r0 + 8 * SAS];
                alf[mt][2] = *(const u32*)&AL[r0 + 8];
                alf[mt][3] = *(const u32*)&AL[r0 + 8 * SAS + 8];
            }
#pragma unroll
            for (int nt = 0; nt < 7; nt++) {
                int c0 = (wn * 56 + nt * 8 + grp) * SAS + kofs;
                bhf[nt][0] = *(const u32*)&BH[c0];
                bhf[nt][1] = *(const u32*)&BH[c0 + 8];
                blf[nt][0] = *(const u32*)&BL[c0];
                blf[nt][1] = *(const u32*)&BL[c0 + 8];
            }
#pragma unroll
            for (int mt = 0; mt < 2; mt++)
#pragma unroll
                for (int nt = 0; nt < 7; nt++)
                    mma16816(acc[mt][nt], ahf[mt], bhf[nt]);
#pragma unroll
            for (int mt = 0; mt < 2; mt++)
#pragma unroll
                for (int nt = 0; nt < 7; nt++)
                    mma16816(acc[mt][nt], alf[mt], bhf[nt]);
#pragma unroll
            for (int mt = 0; mt < 2; mt++)
#pragma unroll
                for (int nt = 0; nt < 7; nt++)
                    mma16816(acc[mt][nt], ahf[mt], blf[nt]);
        }
        __syncthreads();
    }

    // ---------------- epilogue: Z/U update ----------------
    const float* Ubase = Uin + (size_t)b * NPS;
    float* Zo = Zout + (size_t)b * NPS;
    float* Uo = Uout + (size_t)b * NPS;
#pragma unroll
    for (int mt = 0; mt < 2; mt++) {
#pragma unroll
        for (int rr = 0; rr < 2; rr++) {
            int grow = mtb * 128 + wm * 32 + mt * 16 + grp + rr * 8;
            if (grow < NP) {
#pragma unroll
                for (int nt = 0; nt < 7; nt++) {
                    int col = ns * 112 + wn * 56 + nt * 8 + qid * 2;
                    int o = grow * NP + col;
                    float2 u = *(const float2*)&Ubase[o];
                    float x0 = acc[mt][nt][rr * 2 + 0];
                    float x1 = acc[mt][nt][rr * 2 + 1];
                    float z0 = fminf(fmaxf(x0 + u.x, 0.f), 1.f);
                    float z1 = fminf(fmaxf(x1 + u.y, 0.f), 1.f);
                    *(float2*)&Zo[o] = make_float2(z0, z1);
                    *(float2*)&Uo[o] = make_float2(u.x + x0 - z0, u.y + x1 - z1);
                }
            }
        }
    }
}

// ---------------- pooled ----------------
__global__ void k_pool(const float* __restrict__ Zfin) {
    int b = blockIdx.x;
    int tid = threadIdx.x;
    __shared__ float sS[196], sW[196];
    const float* Zb = Zfin + b * NPS;
    if (tid < 196) {
        float s = 0.f;
        const float* row = Zb + tid * NP;
        for (int m = 0; m < 196; m++) s += fabsf(row[m]);
        sS[tid] = s + 1e-10f;
    }
    __syncthreads();
    if (tid < 196) {
        float w = 0.f;
        for (int n = 0; n < 196; n++) w += Zb[n * NP + tid] / sS[n];
        sW[tid] = w * (1.f / 196.f);
    }
    __syncthreads();
    const float* Vb = g_V + b * NP * DIM;
    for (int d = tid; d < DIM; d += 256) {
        float acc = 0.f;
        for (int m = 0; m < 196; m++) acc += sW[m] * Vb[m * DIM + d];
        g_pooled[b * DIM + d] = acc;
    }
}

// ---------------- head ----------------
__global__ void k_head(const float* __restrict__ lg, const float* __restrict__ lb,
                       const float* __restrict__ W, const float* __restrict__ bias,
                       float* __restrict__ out) {
    int b = blockIdx.x;
    int tid = threadIdx.x;
    __shared__ float sx[DIM];
    float s = 0.f, s2 = 0.f;
    for (int d = tid; d < DIM; d += 256) {
        float v = g_pooled[b * DIM + d];
        sx[d] = v; s += v; s2 += v * v;
    }
    block_reduce2(s, s2);
    float mu = s * (1.f / 512.f);
    float rs = rsqrtf(s2 * (1.f / 512.f) - mu * mu + LNEPS);
    __syncthreads();
    for (int d = tid; d < DIM; d += 256) sx[d] = (sx[d] - mu) * rs * lg[d] + lb[d];
    __syncthreads();
    float lgts[4];
    float mx = -1e30f;
#pragma unroll
    for (int t = 0; t < 4; t++) {
        int c = tid + t * 256;
        if (c < NCLS) {
            float acc = bias[c];
            for (int d = 0; d < DIM; d++) acc += sx[d] * W[d * NCLS + c];
            lgts[t] = acc;
            mx = fmaxf(mx, acc);
        } else lgts[t] = -1e30f;
    }
    __shared__ float red[32];
    for (int o = 16; o; o >>= 1) mx = fmaxf(mx, __shfl_xor_sync(0xffffffffu, mx, o));
    if ((tid & 31) == 0) red[tid >> 5] = mx;
    __syncthreads();
    float bm = red[0];
    for (int i = 1; i < 8; i++) bm = fmaxf(bm, red[i]);
    float es = 0.f;
#pragma unroll
    for (int t = 0; t < 4; t++) {
        int c = tid + t * 256;
        if (c < NCLS) { lgts[t] = expf(lgts[t] - bm); es += lgts[t]; }
    }
    float dummy = 0.f;
    block_reduce2(es, dummy);
#pragma unroll
    for (int t = 0; t < 4; t++) {
        int c = tid + t * 256;
        if (c < NCLS) out[b * NCLS + c] = lgts[t] / es;
    }
}

// ---------------- host ----------------
extern "C" void kernel_launch(void* const* d_in, const int* in_sizes, int n_in,
                              void* d_out, int out_size) {
    const float* img    = (const float*)d_in[0];
    const float* ln_pg  = (const float*)d_in[1];
    const float* ln_pb  = (const float*)d_in[2];
    const float* wq_w   = (const float*)d_in[3];
    const float* wq_b   = (const float*)d_in[4];
    const float* lnq_g  = (const float*)d_in[5];
    const float* lnq_b  = (const float*)d_in[6];
    const float* wv_w   = (const float*)d_in[7];
    const float* wv_b   = (const float*)d_in[8];
    const float* lnv_g  = (const float*)d_in[9];
    const float* lnv_b  = (const float*)d_in[10];
    const float* pos    = (const float*)d_in[11];
    const float* mlp_g  = (const float*)d_in[12];
    const float* mlp_b  = (const float*)d_in[13];
    const float* mlp_w  = (const float*)d_in[14];
    const float* mlp_bs = (const float*)d_in[15];
    float* out = (float*)d_out;

    float *px, *pq, *pv, *pa, *pm, *pp, *pz, *pu;
    __nv_bfloat16 *pmh, *pml;
    cudaGetSymbolAddress((void**)&px, g_x);
    cudaGetSymbolAddress((void**)&pq, g_Q);
    cudaGetSymbolAddress((void**)&pv, g_V);
    cudaGetSymbolAddress((void**)&pa, g_A);
    cudaGetSymbolAddress((void**)&pm, g_Minv);
    cudaGetSymbolAddress((void**)&pp, g_P);
    cudaGetSymbolAddress((void**)&pz, g_Zbuf);
    cudaGetSymbolAddress((void**)&pu, g_Ubuf);
    cudaGetSymbolAddress((void**)&pmh, g_MH);
    cudaGetSymbolAddress((void**)&pml, g_ML);
    const int ZSTR = BATCH * NPS + SLK_M;
    float* pz0 = pz;        float* pz1 = pz + ZSTR;
    float* pu0 = pu;        float* pu1 = pu + ZSTR;

    cudaFuncSetAttribute(k_inv, cudaFuncAttributeMaxDynamicSharedMemorySize, 196 * 197 * 4);
    cudaFuncSetAttribute(k_admm_mma, cudaFuncAttributeMaxDynamicSharedMemorySize, ADMM_SMEM);

    k_zero<<<(ZSTR + 255) / 256, 256>>>(pz0, pu0, ZSTR);
    k_patch_ln<<<BATCH * NTOK, 256>>>(img, ln_pg, ln_pb, pos);
    dim3 gp(98, 8);
    k_proj<<<gp, 256>>>(px, wq_w, wq_b, pq);
    k_proj<<<gp, 256>>>(px, wv_w, wv_b, pv);
    k_ln512<<<BATCH * NTOK, 128>>>(pq, lnq_g, lnq_b, 1.0f);
    k_ln512<<<BATCH * NTOK, 128>>>(pv, lnv_g, lnv_b, 1.0f / 196.0f);
    dim3 gg(4, 4, BATCH);
    k_gram<<<gg, 256>>>(pv, pv, pa, 0);
    k_gram<<<gg, 256>>>(pq, pv, pp, 1);
    k_inv<<<BATCH, 512, 196 * 197 * 4>>>(pa, pm);
    k_minv_split<<<(BATCH * NP * KP + 255) / 256, 256>>>(pm);
    dim3 ga(2, 2, BATCH);
    for (int t = 0; t < ITERS; t++) {
        const float* zi = (t & 1) ? pz1 : pz0;
        const float* ui = (t & 1) ? pu1 : pu0;
        float* zo = (t & 1) ? pz0 : pz1;
        float* uo = (t & 1) ? pu0 : pu1;
        k_admm_mma<<<ga, 256, ADMM_SMEM>>>(zi, ui, pp, pmh, pml, zo, uo);
    }
    k_pool<<<BATCH, 256>>>(pz0);
    k_head<<<BATCH, 256>>>(mlp_g, mlp_b, mlp_w, mlp_bs, out);
}